// round 16
// baseline (speedup 1.0000x reference)
#include <cuda_runtime.h>
#include <cuda_bf16.h>
#include <mma.h>
#include <cstdint>
#include <math.h>

using namespace nvcuda;

// Problem constants
#define Bb 8
#define Ss_ 512
#define Dd 768
#define Hh 12
#define DH 64
#define Ee 8
#define DFF 3072
#define MROWS (Bb * Ss_)      // 4096
#define QKVN (Hh * 3 * DH)    // 2304
#define SCALE 0.03608439182435161f
#define EPS 1e-12f

// ---------------------------------------------------------------------------
// scratch (device globals)
// ---------------------------------------------------------------------------
__device__ float g_mean[Ee * Bb * Dd];
__device__ float g_dists[Ee * Bb];
__device__ int   g_sel[Bb];
__device__ float g_att[(size_t)Bb * Ss_ * Dd];
__device__ float g_h[(size_t)Bb * Ss_ * Dd];
__device__ float g_ffn2[(size_t)Bb * Ss_ * Dd];

// bf16 buffers
__device__ __nv_bfloat16 g_ctx_b[(size_t)Ee * Bb * Ss_ * Dd];   // attention output (bf16)
__device__ __nv_bfloat16 g_qkv_h[(size_t)Ee * MROWS * QKVN];
__device__ __nv_bfloat16 g_hid_h[(size_t)MROWS * Dd],  g_hid_l[(size_t)MROWS * Dd];
__device__ __nv_bfloat16 g_Wqkv_h[(size_t)Ee * QKVN * Dd], g_Wqkv_l[(size_t)Ee * QKVN * Dd];
__device__ __nv_bfloat16 g_Wd_h[(size_t)Ee * Dd * Dd],     g_Wd_l[(size_t)Ee * Dd * Dd];
__device__ __nv_bfloat16 g_W1_h[(size_t)Ee * DFF * Dd],    g_W1_l[(size_t)Ee * DFF * Dd];
__device__ __nv_bfloat16 g_W2_h[(size_t)Ee * Dd * DFF],    g_W2_l[(size_t)Ee * Dd * DFF];
__device__ __nv_bfloat16 g_hb_h[(size_t)Bb * Ss_ * Dd],    g_hb_l[(size_t)Bb * Ss_ * Dd];
__device__ __nv_bfloat16 g_f1_h[(size_t)Bb * Ss_ * DFF],   g_f1_l[(size_t)Bb * Ss_ * DFF];

// ---------------------------------------------------------------------------
// cp.async helpers
// ---------------------------------------------------------------------------
__device__ __forceinline__ void cp16(uint32_t s, const void* g) {
    asm volatile("cp.async.cg.shared.global [%0], [%1], 16;" :: "r"(s), "l"(g));
}
__device__ __forceinline__ uint32_t smem_u32(const void* p) {
    uint32_t a;
    asm("{ .reg .u64 t; cvta.to.shared.u64 t, %1; cvt.u32.u64 %0, t; }" : "=r"(a) : "l"(p));
    return a;
}
__device__ __forceinline__ uint32_t pack2(float a, float b) {
    return (uint32_t)__bfloat16_as_ushort(__float2bfloat16(a)) |
           ((uint32_t)__bfloat16_as_ushort(__float2bfloat16(b)) << 16);
}

// ---------------------------------------------------------------------------
// fp32 -> (bf16 hi, bf16 lo)   (vectorized x4)
// ---------------------------------------------------------------------------
__global__ void split_kernel(const float* __restrict__ s, __nv_bfloat16* __restrict__ h,
                             __nv_bfloat16* __restrict__ l, int n4)
{
    int i = blockIdx.x * 256 + threadIdx.x;
    if (i < n4) {
        float4 x = ((const float4*)s)[i];
        __nv_bfloat16 h0 = __float2bfloat16(x.x), h1 = __float2bfloat16(x.y);
        __nv_bfloat16 h2 = __float2bfloat16(x.z), h3 = __float2bfloat16(x.w);
        __nv_bfloat16 l0 = __float2bfloat16(x.x - __bfloat162float(h0));
        __nv_bfloat16 l1 = __float2bfloat16(x.y - __bfloat162float(h1));
        __nv_bfloat16 l2 = __float2bfloat16(x.z - __bfloat162float(h2));
        __nv_bfloat16 l3 = __float2bfloat16(x.w - __bfloat162float(h3));
        ushort4 hv, lv;
        hv.x = __bfloat16_as_ushort(h0); hv.y = __bfloat16_as_ushort(h1);
        hv.z = __bfloat16_as_ushort(h2); hv.w = __bfloat16_as_ushort(h3);
        lv.x = __bfloat16_as_ushort(l0); lv.y = __bfloat16_as_ushort(l1);
        lv.z = __bfloat16_as_ushort(l2); lv.w = __bfloat16_as_ushort(l3);
        ((ushort4*)h)[i] = hv;
        ((ushort4*)l)[i] = lv;
    }
}

// ---------------------------------------------------------------------------
// WMMA GEMM, 2-stage cp.async double buffer, 2 CTAs/SM, vectorized epilogue.
// MODE 0: QKV 1-pass bf16, K-chunk 64
// MODE 1: dense 2-pass (A bf16 ctx, B hi/lo), K-chunk 64, fp32 out
// MODE 2: FFN1 3-pass, gelu, bf16 hi/lo out  MODE 3: FFN2 3-pass, fp32 out
// ---------------------------------------------------------------------------
template <int MODE>
__global__ __launch_bounds__(256, 2) void tc_gemm(const float* __restrict__ biasb, int zofs)
{
    constexpr int NPASS = (MODE == 0) ? 1 : ((MODE == 1) ? 2 : 3);
    constexpr int NBUF  = (MODE == 0) ? 2 : ((MODE == 1) ? 3 : 4);
    constexpr int KC    = (MODE <= 1) ? 64 : 32;
    constexpr int LDTc  = KC + 8;
    constexpr int BUFB  = 128 * LDTc * 2;      // bytes per matrix buffer
    constexpr int EBUF  = 128 * LDTc;          // elements per buffer
    constexpr int STG   = NBUF * BUFB;
    constexpr int SEGN  = KC / 8;
    constexpr int REPS  = (128 * SEGN) / 256;
    constexpr int BOFF_AL = 1;                          // only NPASS==3
    constexpr int BOFF_BH = (NPASS == 3) ? 2 : 1;
    constexpr int BOFF_BL = (NPASS == 3) ? 3 : 2;

    extern __shared__ char smem[];
    uint32_t sb = smem_u32(smem);

    int tid = threadIdx.x;
    int wid = tid >> 5, lane = tid & 31;
    int z = blockIdx.z + zofs;
    int m0 = blockIdx.y * 128, n0 = blockIdx.x * 128;

    const __nv_bfloat16 *A_h, *A_l = nullptr, *B_h, *B_l = nullptr;
    const float* bias = nullptr;
    float* Cf = nullptr;
    __nv_bfloat16 *Ch = nullptr, *Cl = nullptr;
    int K, N;
    if (MODE == 0) {
        K = Dd; N = QKVN;
        A_h = g_hid_h;
        B_h = g_Wqkv_h + (size_t)z * QKVN * Dd;
        Ch = g_qkv_h + (size_t)z * MROWS * QKVN;
    } else {
        int e = g_sel[z];
        if (MODE == 1) {
            K = Dd; N = Dd;
            A_h = g_ctx_b + ((size_t)(e * Bb + z)) * Ss_ * Dd;
            B_h = g_Wd_h + (size_t)e * Dd * Dd;  B_l = g_Wd_l + (size_t)e * Dd * Dd;
            bias = biasb + (size_t)e * Dd;
            Cf = g_att + (size_t)z * Ss_ * Dd;
        } else if (MODE == 2) {
            K = Dd; N = DFF;
            A_h = g_hb_h + (size_t)z * Ss_ * Dd;  A_l = g_hb_l + (size_t)z * Ss_ * Dd;
            B_h = g_W1_h + (size_t)e * DFF * Dd;  B_l = g_W1_l + (size_t)e * DFF * Dd;
            bias = biasb + (size_t)e * DFF;
            Ch = g_f1_h + (size_t)z * Ss_ * DFF;  Cl = g_f1_l + (size_t)z * Ss_ * DFF;
        } else {
            K = DFF; N = Dd;
            A_h = g_f1_h + (size_t)z * Ss_ * DFF; A_l = g_f1_l + (size_t)z * Ss_ * DFF;
            B_h = g_W2_h + (size_t)e * Dd * DFF;  B_l = g_W2_l + (size_t)e * Dd * DFF;
            bias = biasb + (size_t)e * Dd;
            Cf = g_ffn2 + (size_t)z * Ss_ * Dd;
        }
    }

    int wm = wid >> 2, wn = wid & 3;

    wmma::fragment<wmma::accumulator, 16, 16, 16, float> acc[4][2];
    #pragma unroll
    for (int i = 0; i < 4; i++)
        #pragma unroll
        for (int j = 0; j < 2; j++) wmma::fill_fragment(acc[i][j], 0.f);

    int row_[REPS], seg_[REPS];
    uint32_t sbo_[REPS];
    #pragma unroll
    for (int rep = 0; rep < REPS; rep++) {
        int idx = tid + rep * 256;
        row_[rep] = idx / SEGN; seg_[rep] = (idx % SEGN) * 8;
        sbo_[rep] = (uint32_t)(row_[rep] * LDTc + seg_[rep]) * 2;
    }

    const __nv_bfloat16* gA_h = A_h + (size_t)m0 * K;
    const __nv_bfloat16* gB_h = B_h + (size_t)n0 * K;
    const __nv_bfloat16* gA_l = (NPASS == 3) ? A_l + (size_t)m0 * K : nullptr;
    const __nv_bfloat16* gB_l = (NPASS >= 2) ? B_l + (size_t)n0 * K : nullptr;

    int KT = K / KC;

    #define ISSUE_STAGE(kcI, st) do {                                          \
        uint32_t base_ = sb + (uint32_t)(st) * STG;                            \
        _Pragma("unroll")                                                      \
        for (int rep = 0; rep < REPS; rep++) {                                 \
            size_t goff_ = (size_t)row_[rep] * K + (size_t)(kcI) * KC + seg_[rep]; \
            uint32_t so_ = base_ + sbo_[rep];                                  \
            cp16(so_, gA_h + goff_);                                           \
            if (NPASS == 3) cp16(so_ + BOFF_AL * BUFB, gA_l + goff_);          \
            cp16(so_ + BOFF_BH * BUFB, gB_h + goff_);                          \
            if (NPASS >= 2) cp16(so_ + BOFF_BL * BUFB, gB_l + goff_);          \
        }                                                                      \
        asm volatile("cp.async.commit_group;" ::: "memory");                   \
    } while (0)

    ISSUE_STAGE(0, 0);
    ISSUE_STAGE(1, 1);

    for (int kc = 0; kc < KT; kc++) {
        int st = kc & 1;
        if (kc + 1 < KT) asm volatile("cp.async.wait_group 1;" ::: "memory");
        else             asm volatile("cp.async.wait_group 0;" ::: "memory");
        __syncthreads();

        __nv_bfloat16* Ah = (__nv_bfloat16*)(smem + st * STG);
        __nv_bfloat16* Al = Ah + BOFF_AL * EBUF;
        __nv_bfloat16* Bh = Ah + BOFF_BH * EBUF;
        __nv_bfloat16* Bl = Ah + BOFF_BL * EBUF;
        #pragma unroll
        for (int kk = 0; kk < KC / 16; kk++) {
            int ko = kk * 16;
            wmma::fragment<wmma::matrix_a, 16, 16, 16, __nv_bfloat16, wmma::row_major> fa_h[4], fa_l[4];
            wmma::fragment<wmma::matrix_b, 16, 16, 16, __nv_bfloat16, wmma::col_major> fb_h[2], fb_l[2];
            #pragma unroll
            for (int i = 0; i < 4; i++) {
                wmma::load_matrix_sync(fa_h[i], &Ah[(wm * 64 + i * 16) * LDTc + ko], LDTc);
                if (NPASS == 3) wmma::load_matrix_sync(fa_l[i], &Al[(wm * 64 + i * 16) * LDTc + ko], LDTc);
            }
            #pragma unroll
            for (int j = 0; j < 2; j++) {
                wmma::load_matrix_sync(fb_h[j], &Bh[(wn * 32 + j * 16) * LDTc + ko], LDTc);
                if (NPASS >= 2) wmma::load_matrix_sync(fb_l[j], &Bl[(wn * 32 + j * 16) * LDTc + ko], LDTc);
            }
            #pragma unroll
            for (int i = 0; i < 4; i++)
                #pragma unroll
                for (int j = 0; j < 2; j++) {
                    wmma::mma_sync(acc[i][j], fa_h[i], fb_h[j], acc[i][j]);
                    if (NPASS >= 2) wmma::mma_sync(acc[i][j], fa_h[i], fb_l[j], acc[i][j]);
                    if (NPASS == 3) wmma::mma_sync(acc[i][j], fa_l[i], fb_h[j], acc[i][j]);
                }
        }
        if (kc + 2 < KT) {
            __syncthreads();
            ISSUE_STAGE(kc + 2, st);
        }
    }
    #undef ISSUE_STAGE

    __syncthreads();

    float* Stage = (float*)smem + wid * 256;
    int r = lane >> 1, c0 = (lane & 1) * 8;
    #pragma unroll
    for (int i = 0; i < 4; i++)
        #pragma unroll
        for (int j = 0; j < 2; j++) {
            wmma::store_matrix_sync(Stage, acc[i][j], 16, wmma::mem_row_major);
            __syncwarp();
            int gm = m0 + wm * 64 + i * 16 + r;
            int gn = n0 + wn * 32 + j * 16 + c0;
            const float* srow = Stage + r * 16 + c0;
            float vv[8];
            #pragma unroll
            for (int c = 0; c < 8; c++) {
                float v = srow[c];
                if (MODE != 0) v += bias[gn + c];
                if (MODE == 2) v = 0.5f * v * (1.f + erff(v * 0.7071067811865475f));
                vv[c] = v;
            }
            size_t ob = (size_t)gm * N + gn;
            if (MODE == 0) {
                uint4 pk;
                pk.x = pack2(vv[0], vv[1]); pk.y = pack2(vv[2], vv[3]);
                pk.z = pack2(vv[4], vv[5]); pk.w = pack2(vv[6], vv[7]);
                *(uint4*)&Ch[ob] = pk;
            } else if (MODE == 2) {
                uint32_t ph[4], pl[4];
                #pragma unroll
                for (int q = 0; q < 4; q++) {
                    __nv_bfloat16 h0 = __float2bfloat16(vv[2 * q]);
                    __nv_bfloat16 h1 = __float2bfloat16(vv[2 * q + 1]);
                    __nv_bfloat16 l0 = __float2bfloat16(vv[2 * q] - __bfloat162float(h0));
                    __nv_bfloat16 l1 = __float2bfloat16(vv[2 * q + 1] - __bfloat162float(h1));
                    ph[q] = __bfloat16_as_ushort(h0) | ((uint32_t)__bfloat16_as_ushort(h1) << 16);
                    pl[q] = __bfloat16_as_ushort(l0) | ((uint32_t)__bfloat16_as_ushort(l1) << 16);
                }
                uint4 vh; vh.x = ph[0]; vh.y = ph[1]; vh.z = ph[2]; vh.w = ph[3];
                uint4 vl; vl.x = pl[0]; vl.y = pl[1]; vl.z = pl[2]; vl.w = pl[3];
                *(uint4*)&Ch[ob] = vh;
                *(uint4*)&Cl[ob] = vl;
            } else {
                float4 f0; f0.x = vv[0]; f0.y = vv[1]; f0.z = vv[2]; f0.w = vv[3];
                float4 f1; f1.x = vv[4]; f1.y = vv[5]; f1.z = vv[6]; f1.w = vv[7];
                *(float4*)&Cf[ob] = f0;
                *(float4*)&Cf[ob + 4] = f1;
            }
            __syncwarp();
        }
}

// ---------------------------------------------------------------------------
// Pure-bf16 WMMA attention, cp.async 2-stage K/V ring, V overlaps softmax,
// Q fragments hoisted, bf16 ctx output. smem 90,112 B -> 2 CTAs/SM.
// ---------------------------------------------------------------------------
#define QT 32
#define SLD 524
#define PLD 1048
#define ATT_SC  0
#define ATT_Q   67072
#define ATT_K0  71680
#define KSTG2   9216
#define ATT_TOT 90112

__global__ __launch_bounds__(256, 2) void attn2_kernel(const int* __restrict__ mask, int ebofs)
{
    extern __shared__ char smem[];
    uint32_t sb = smem_u32(smem);
    float* Sc = (float*)(smem + ATT_SC);
    __nv_bfloat16* P = (__nv_bfloat16*)(smem + ATT_SC);
    __nv_bfloat16* Qs = (__nv_bfloat16*)(smem + ATT_Q);

    int q0 = blockIdx.x * QT;
    int h  = blockIdx.y;
    int eb = blockIdx.z + ebofs;
    int e = eb >> 3, b = eb & 7;
    int tid = threadIdx.x;
    int wid = tid >> 5, lane = tid & 31;
    int wr = wid >> 2, wc = wid & 3;

    const __nv_bfloat16* baseh = g_qkv_h + ((size_t)e * MROWS + b * Ss_) * QKVN + h * 192;

    float mb[16];
    #pragma unroll
    for (int t = 0; t < 16; t++)
        mb[t] = (mask[b * Ss_ + lane + t * 32] == 0) ? -1e30f : 0.f;

    #define ISSUE_KV(srcOff, ktI, st) do {                                       \
        uint32_t kb_ = sb + ATT_K0 + (uint32_t)(st) * KSTG2;                     \
        _Pragma("unroll")                                                        \
        for (int rep = 0; rep < 2; rep++) {                                      \
            int idx = tid + rep * 256;                                           \
            int row = idx >> 3, seg = (idx & 7) * 8;                             \
            size_t go = (size_t)((ktI) * 64 + row) * QKVN + (srcOff) + seg;      \
            cp16(kb_ + (uint32_t)(row * 72 + seg) * 2, baseh + go);              \
        }                                                                        \
    } while (0)

    {
        int row = tid >> 3, seg = (tid & 7) * 8;
        size_t go = (size_t)(q0 + row) * QKVN + seg;
        cp16(sb + ATT_Q + (uint32_t)(row * 72 + seg) * 2, baseh + go);
    }
    ISSUE_KV(64, 0, 0);
    asm volatile("cp.async.commit_group;" ::: "memory");
    ISSUE_KV(64, 1, 1);
    asm volatile("cp.async.commit_group;" ::: "memory");

    wmma::fragment<wmma::matrix_a, 16, 16, 16, __nv_bfloat16, wmma::row_major> qf[4];

    // ---- S = Q K^T ----
    for (int kt = 0; kt < 8; kt++) {
        int st = kt & 1;
        if (kt + 1 < 8) asm volatile("cp.async.wait_group 1;" ::: "memory");
        else            asm volatile("cp.async.wait_group 0;" ::: "memory");
        __syncthreads();
        if (kt == 0) {
            #pragma unroll
            for (int kf = 0; kf < 4; kf++)
                wmma::load_matrix_sync(qf[kf], &Qs[(wr * 16) * 72 + kf * 16], 72);
        }

        __nv_bfloat16* Kh = (__nv_bfloat16*)(smem + ATT_K0 + st * KSTG2);

        wmma::fragment<wmma::accumulator, 16, 16, 16, float> acc;
        wmma::fill_fragment(acc, 0.f);
        #pragma unroll
        for (int kf = 0; kf < 4; kf++) {
            wmma::fragment<wmma::matrix_b, 16, 16, 16, __nv_bfloat16, wmma::col_major> kh;
            wmma::load_matrix_sync(kh, &Kh[(wc * 16) * 72 + kf * 16], 72);
            wmma::mma_sync(acc, qf[kf], kh, acc);
        }
        wmma::store_matrix_sync(&Sc[(wr * 16) * SLD + kt * 64 + wc * 16], acc, SLD, wmma::mem_row_major);

        if (kt + 2 < 8) {
            __syncthreads();
            ISSUE_KV(64, kt + 2, st);
            asm volatile("cp.async.commit_group;" ::: "memory");
        }
    }
    __syncthreads();

    ISSUE_KV(128, 0, 0);
    asm volatile("cp.async.commit_group;" ::: "memory");
    ISSUE_KV(128, 1, 1);
    asm volatile("cp.async.commit_group;" ::: "memory");

    // ---- softmax; write P (bf16) aliased into this row's own Sc bytes ----
    {
        #pragma unroll
        for (int rr = 0; rr < 4; rr++) {
            int row = wid * 4 + rr;
            const float* srow = Sc + row * SLD;
            float v[16];
            float mx = -INFINITY;
            #pragma unroll
            for (int t = 0; t < 16; t++) {
                int j = lane + t * 32;
                v[t] = srow[j] * SCALE + mb[t];
                mx = fmaxf(mx, v[t]);
            }
            #pragma unroll
            for (int o = 16; o; o >>= 1) mx = fmaxf(mx, __shfl_xor_sync(~0u, mx, o));
            float sum = 0.f;
            #pragma unroll
            for (int t = 0; t < 16; t++) { v[t] = __expf(v[t] - mx); sum += v[t]; }
            #pragma unroll
            for (int o = 16; o; o >>= 1) sum += __shfl_xor_sync(~0u, sum, o);
            float inv = 1.f / sum;
            __nv_bfloat16* prow = P + row * PLD;
            #pragma unroll
            for (int t = 0; t < 16; t++) {
                int j = lane + t * 32;
                prow[j] = __float2bfloat16(v[t] * inv);
            }
        }
    }

    // ---- O = P V ----
    wmma::fragment<wmma::accumulator, 16, 16, 16, float> oacc;
    wmma::fill_fragment(oacc, 0.f);
    for (int vt = 0; vt < 8; vt++) {
        int st = vt & 1;
        if (vt + 1 < 8) asm volatile("cp.async.wait_group 1;" ::: "memory");
        else            asm volatile("cp.async.wait_group 0;" ::: "memory");
        __syncthreads();

        __nv_bfloat16* Vh = (__nv_bfloat16*)(smem + ATT_K0 + st * KSTG2);

        #pragma unroll
        for (int kf = 0; kf < 4; kf++) {
            wmma::fragment<wmma::matrix_a, 16, 16, 16, __nv_bfloat16, wmma::row_major> ph;
            wmma::fragment<wmma::matrix_b, 16, 16, 16, __nv_bfloat16, wmma::row_major> vh;
            wmma::load_matrix_sync(ph, &P[(wr * 16) * PLD + vt * 64 + kf * 16], PLD);
            wmma::load_matrix_sync(vh, &Vh[(kf * 16) * 72 + wc * 16], 72);
            wmma::mma_sync(oacc, ph, vh, oacc);
        }
        if (vt + 2 < 8) {
            __syncthreads();
            ISSUE_KV(128, vt + 2, st);
            asm volatile("cp.async.commit_group;" ::: "memory");
        }
    }
    #undef ISSUE_KV

    // ---- epilogue: stage oacc, write bf16 ctx (vectorized) ----
    __syncthreads();   // all P reads done before overwriting Sc region
    {
        float* StageW = (float*)smem + wid * 256;
        wmma::store_matrix_sync(StageW, oacc, 16, wmma::mem_row_major);
        __syncwarp();
        int r = lane >> 1, c0 = (lane & 1) * 8;
        const float* srow = StageW + r * 16 + c0;
        uint4 pk;
        pk.x = pack2(srow[0], srow[1]); pk.y = pack2(srow[2], srow[3]);
        pk.z = pack2(srow[4], srow[5]); pk.w = pack2(srow[6], srow[7]);
        __nv_bfloat16* op = g_ctx_b + ((size_t)eb * Ss_ + q0 + wr * 16 + r) * Dd + h * 64 + wc * 16 + c0;
        *(uint4*)op = pk;
    }
}

// ---------------------------------------------------------------------------
// routing
// ---------------------------------------------------------------------------
__global__ void zeroroute_kernel()
{
    int i = blockIdx.x * 256 + threadIdx.x;
    if (i < Ee * Bb * Dd) g_mean[i] = 0.f;
    if (i < Ee * Bb) g_dists[i] = 0.f;
}

__global__ void meanctx_kernel(int ebofs)
{
    int eb = blockIdx.x + ebofs;
    int chunk = blockIdx.y;
    int d = threadIdx.x;
    const __nv_bfloat16* p = g_ctx_b + ((size_t)eb * Ss_ + chunk * 64) * Dd + d;
    float s = 0.f;
    for (int i = 0; i < 64; i++) s += __bfloat162float(p[(size_t)i * Dd]);
    atomicAdd(&g_mean[eb * Dd + d], s * (1.f / Ss_));
}

__global__ __launch_bounds__(256) void featdist_kernel(const float* __restrict__ Wd,
                                                       const float* __restrict__ bd,
                                                       const float* __restrict__ centers,
                                                       int ebofs)
{
    int eb = blockIdx.x + ebofs, e = eb >> 3;
    int chunk = blockIdx.y;
    __shared__ float mn[Dd];
    int tid = threadIdx.x;
    for (int d = tid; d < Dd; d += 256) mn[d] = g_mean[eb * Dd + d];
    __syncthreads();
    int w = tid >> 5, lane = tid & 31;
    float sq = 0.f;
    for (int i = 0; i < 12; i++) {
        int d = chunk * 96 + w * 12 + i;
        const float* wrow = Wd + ((size_t)e * Dd + d) * Dd;
        float p = 0.f;
        for (int k = lane; k < Dd; k += 32) p += wrow[k] * mn[k];
        #pragma unroll
        for (int o = 16; o; o >>= 1) p += __shfl_xor_sync(~0u, p, o);
        if (lane == 0) {
            float f = p + bd[e * Dd + d] - centers[e * Dd + d];
            sq += f * f;
        }
    }
    if (lane == 0) atomicAdd(&g_dists[eb], sq);
}

__global__ void argmin_kernel()
{
    int b = threadIdx.x;
    if (b < Bb) {
        float best = g_dists[b];
        int bi = 0;
        for (int e = 1; e < Ee; e++) {
            float v = g_dists[e * Bb + b];
            if (v < best) { best = v; bi = e; }
        }
        g_sel[b] = bi;
    }
}

// ---------------------------------------------------------------------------
// residual + layernorm
// ---------------------------------------------------------------------------
__device__ __forceinline__ float block_sum_768(float v, float* red, int tid)
{
    __syncthreads();
    #pragma unroll
    for (int o = 16; o; o >>= 1) v += __shfl_xor_sync(~0u, v, o);
    if ((tid & 31) == 0) red[tid >> 5] = v;
    __syncthreads();
    if (tid < 8) {
        float t = red[tid];
        #pragma unroll
        for (int o = 4; o; o >>= 1) t += __shfl_xor_sync(0xffu, t, o);
        if (tid == 0) red[0] = t;
    }
    __syncthreads();
    return red[0];
}

template <int WHICH>
__global__ __launch_bounds__(256) void residual_ln_kernel(
    const float* __restrict__ X, const float* __restrict__ gamma_,
    const float* __restrict__ beta_, float* __restrict__ Out)
{
    __shared__ float red[8];
    int row = blockIdx.x;
    int b = row >> 9;
    int e = g_sel[b];
    const float* gamma = gamma_ + e * Dd;
    const float* beta  = beta_  + e * Dd;
    const float* xr; const float* yr; float* orow;
    if (WHICH == 1) {
        xr = X + (size_t)row * Dd;
        yr = g_att + (size_t)row * Dd;
        orow = g_h + (size_t)row * Dd;
    } else {
        xr = g_h + (size_t)row * Dd;
        yr = g_ffn2 + (size_t)row * Dd;
        orow = Out + (size_t)row * Dd;
    }
    int tid = threadIdx.x;
    float v0 = xr[tid] + yr[tid];
    float v1 = xr[tid + 256] + yr[tid + 256];
    float v2 = xr[tid + 512] + yr[tid + 512];
    float mean = block_sum_768(v0 + v1 + v2, red, tid) * (1.f / Dd);
    float d0 = v0 - mean, d1 = v1 - mean, d2 = v2 - mean;
    float var = block_sum_768(d0 * d0 + d1 * d1 + d2 * d2, red, tid) * (1.f / Dd);
    float inv = rsqrtf(var + EPS);
    float o0 = d0 * inv * gamma[tid]       + beta[tid];
    float o1 = d1 * inv * gamma[tid + 256] + beta[tid + 256];
    float o2 = d2 * inv * gamma[tid + 512] + beta[tid + 512];
    orow[tid]       = o0;
    orow[tid + 256] = o1;
    orow[tid + 512] = o2;
    if (WHICH == 1) {
        __nv_bfloat16* hh = g_hb_h + (size_t)row * Dd;
        __nv_bfloat16* hl = g_hb_l + (size_t)row * Dd;
        __nv_bfloat16 h0 = __float2bfloat16(o0);
        __nv_bfloat16 h1 = __float2bfloat16(o1);
        __nv_bfloat16 h2 = __float2bfloat16(o2);
        hh[tid] = h0;       hl[tid]       = __float2bfloat16(o0 - __bfloat162float(h0));
        hh[tid + 256] = h1; hl[tid + 256] = __float2bfloat16(o1 - __bfloat162float(h1));
        hh[tid + 512] = h2; hl[tid + 512] = __float2bfloat16(o2 - __bfloat162float(h2));
    }
}

// ---------------------------------------------------------------------------
// launch
// ---------------------------------------------------------------------------
#define SMEM_G1 (2 * 2 * (128 * 72 * 2))   // 73728  (QKV, 2 bufs, KC64)
#define SMEM_GD (2 * 3 * (128 * 72 * 2))   // 110592 (dense, 3 bufs, KC64)
#define SMEM_G3 (2 * 4 * (128 * 40 * 2))   // 81920  (FFN, 4 bufs, KC32)

extern "C" void kernel_launch(void* const* d_in, const int* in_sizes, int n_in,
                              void* d_out, int out_size)
{
    const float* hidden  = (const float*)d_in[0];
    const int*   mask    = (const int*)d_in[1];
    const float* Wqkv    = (const float*)d_in[2];
    const float* Wd      = (const float*)d_in[3];
    const float* bd      = (const float*)d_in[4];
    const float* ln1g    = (const float*)d_in[5];
    const float* ln1b    = (const float*)d_in[6];
    const float* W1      = (const float*)d_in[7];
    const float* b1      = (const float*)d_in[8];
    const float* W2      = (const float*)d_in[9];
    const float* b2      = (const float*)d_in[10];
    const float* ln2g    = (const float*)d_in[11];
    const float* ln2b    = (const float*)d_in[12];
    const float* centers = (const float*)d_in[13];
    float* out = (float*)d_out;

    static bool init_done = false;
    static cudaStream_t sB, sQ;
    static cudaEvent_t evFork, evJoin, evSplit, evQ[Ee], evA[Ee];
    if (!init_done) {
        cudaFuncSetAttribute(attn2_kernel, cudaFuncAttributeMaxDynamicSharedMemorySize, ATT_TOT);
        cudaFuncSetAttribute(tc_gemm<0>, cudaFuncAttributeMaxDynamicSharedMemorySize, SMEM_G1);
        cudaFuncSetAttribute(tc_gemm<1>, cudaFuncAttributeMaxDynamicSharedMemorySize, SMEM_GD);
        cudaFuncSetAttribute(tc_gemm<2>, cudaFuncAttributeMaxDynamicSharedMemorySize, SMEM_G3);
        cudaFuncSetAttribute(tc_gemm<3>, cudaFuncAttributeMaxDynamicSharedMemorySize, SMEM_G3);
        cudaStreamCreateWithFlags(&sB, cudaStreamNonBlocking);
        cudaStreamCreateWithFlags(&sQ, cudaStreamNonBlocking);
        cudaEventCreateWithFlags(&evFork, cudaEventDisableTiming);
        cudaEventCreateWithFlags(&evJoin, cudaEventDisableTiming);
        cudaEventCreateWithFlags(&evSplit, cudaEventDisableTiming);
        for (int e = 0; e < Ee; e++) {
            cudaEventCreateWithFlags(&evQ[e], cudaEventDisableTiming);
            cudaEventCreateWithFlags(&evA[e], cudaEventDisableTiming);
        }
        init_done = true;
    }

    __nv_bfloat16 *hid_h, *hid_l, *wq_h, *wq_l, *wd_h, *wd_l, *w1_h, *w1_l, *w2_h, *w2_l;
    cudaGetSymbolAddress((void**)&hid_h, g_hid_h);  cudaGetSymbolAddress((void**)&hid_l, g_hid_l);
    cudaGetSymbolAddress((void**)&wq_h, g_Wqkv_h);  cudaGetSymbolAddress((void**)&wq_l, g_Wqkv_l);
    cudaGetSymbolAddress((void**)&wd_h, g_Wd_h);    cudaGetSymbolAddress((void**)&wd_l, g_Wd_l);
    cudaGetSymbolAddress((void**)&w1_h, g_W1_h);    cudaGetSymbolAddress((void**)&w1_l, g_W1_l);
    cudaGetSymbolAddress((void**)&w2_h, g_W2_h);    cudaGetSymbolAddress((void**)&w2_l, g_W2_l);

    int n_hid = MROWS * Dd / 4;
    int n_wq  = Ee * QKVN * Dd / 4;
    int n_wd  = Ee * Dd * Dd / 4;
    int n_w1  = Ee * DFF * Dd / 4;
    int n_w2  = Ee * Dd * DFF / 4;

    cudaEventRecord(evFork, 0);

    // ---- main stream: input splits ----
    split_kernel<<<(n_hid + 255) / 256, 256>>>(hidden, hid_h, hid_l, n_hid);
    split_kernel<<<(n_wq  + 255) / 256, 256>>>(Wqkv,  wq_h,  wq_l,  n_wq);
    cudaEventRecord(evSplit, 0);

    // ---- stream Q: per-expert QKV GEMMs (serial on sQ) ----
    cudaStreamWaitEvent(sQ, evSplit, 0);
    for (int e = 0; e < Ee; e++) {
        tc_gemm<0><<<dim3(QKVN / 128, MROWS / 128, 1), 256, SMEM_G1, sQ>>>(nullptr, e);
        cudaEventRecord(evQ[e], sQ);
    }

    // ---- main stream: per-expert attention, each gated on its QKV ----
    for (int e = 0; e < Ee; e++) {
        cudaStreamWaitEvent(0, evQ[e], 0);
        attn2_kernel<<<dim3(Ss_ / QT, Hh, Bb), 256, ATT_TOT>>>(mask, e * Bb);
        cudaEventRecord(evA[e], 0);
    }

    // ---- side stream: zeroroute, weight splits, per-expert meanctx+featdist ----
    cudaStreamWaitEvent(sB, evFork, 0);
    zeroroute_kernel<<<(Ee * Bb * Dd + 255) / 256, 256, 0, sB>>>();
    split_kernel<<<(n_wd + 255) / 256, 256, 0, sB>>>(Wd, wd_h, wd_l, n_wd);
    split_kernel<<<(n_w1 + 255) / 256, 256, 0, sB>>>(W1, w1_h, w1_l, n_w1);
    split_kernel<<<(n_w2 + 255) / 256, 256, 0, sB>>>(W2, w2_h, w2_l, n_w2);
    for (int e = 0; e < Ee; e++) {
        cudaStreamWaitEvent(sB, evA[e], 0);
        meanctx_kernel<<<dim3(Bb, 8), Dd, 0, sB>>>(e * Bb);
        featdist_kernel<<<dim3(Bb, 8), 256, 0, sB>>>(Wd, bd, centers, e * Bb);
    }
    argmin_kernel<<<1, 32, 0, sB>>>();
    cudaEventRecord(evJoin, sB);

    cudaStreamWaitEvent(0, evJoin, 0);

    // selected-expert path
    tc_gemm<1><<<dim3(Dd / 128, Ss_ / 128, Bb), 256, SMEM_GD>>>(bd, 0);
    residual_ln_kernel<1><<<MROWS, 256>>>(hidden, ln1g, ln1b, nullptr);
    tc_gemm<2><<<dim3(DFF / 128, Ss_ / 128, Bb), 256, SMEM_G3>>>(b1, 0);
    tc_gemm<3><<<dim3(Dd / 128, Ss_ / 128, Bb), 256, SMEM_G3>>>(b2, 0);
    residual_ln_kernel<2><<<MROWS, 256>>>(nullptr, ln2g, ln2b, out);
}

// round 17
// speedup vs baseline: 1.0790x; 1.0790x over previous
#include <cuda_runtime.h>
#include <cuda_bf16.h>
#include <mma.h>
#include <cstdint>
#include <math.h>

using namespace nvcuda;

// Problem constants
#define Bb 8
#define Ss_ 512
#define Dd 768
#define Hh 12
#define DH 64
#define Ee 8
#define DFF 3072
#define MROWS (Bb * Ss_)      // 4096
#define QKVN (Hh * 3 * DH)    // 2304
#define SCALE 0.03608439182435161f
#define EPS 1e-12f

// ---------------------------------------------------------------------------
// scratch (device globals)
// ---------------------------------------------------------------------------
__device__ float g_mean[Ee * Bb * Dd];
__device__ float g_dists[Ee * Bb];
__device__ int   g_sel[Bb];
__device__ float g_att[(size_t)Bb * Ss_ * Dd];
__device__ float g_h[(size_t)Bb * Ss_ * Dd];
__device__ float g_ffn2[(size_t)Bb * Ss_ * Dd];

// bf16 buffers
__device__ __nv_bfloat16 g_ctx_b[(size_t)Ee * Bb * Ss_ * Dd];   // attention output (bf16)
__device__ __nv_bfloat16 g_qkv_h[(size_t)Ee * MROWS * QKVN];
__device__ __nv_bfloat16 g_hid_h[(size_t)MROWS * Dd],  g_hid_l[(size_t)MROWS * Dd];
__device__ __nv_bfloat16 g_Wqkv_h[(size_t)Ee * QKVN * Dd], g_Wqkv_l[(size_t)Ee * QKVN * Dd];
__device__ __nv_bfloat16 g_Wd_h[(size_t)Ee * Dd * Dd],     g_Wd_l[(size_t)Ee * Dd * Dd];
__device__ __nv_bfloat16 g_W1_h[(size_t)Ee * DFF * Dd],    g_W1_l[(size_t)Ee * DFF * Dd];
__device__ __nv_bfloat16 g_W2_h[(size_t)Ee * Dd * DFF],    g_W2_l[(size_t)Ee * Dd * DFF];
__device__ __nv_bfloat16 g_hb_h[(size_t)Bb * Ss_ * Dd],    g_hb_l[(size_t)Bb * Ss_ * Dd];
__device__ __nv_bfloat16 g_f1_h[(size_t)Bb * Ss_ * DFF],   g_f1_l[(size_t)Bb * Ss_ * DFF];

// ---------------------------------------------------------------------------
// cp.async helpers
// ---------------------------------------------------------------------------
__device__ __forceinline__ void cp16(uint32_t s, const void* g) {
    asm volatile("cp.async.cg.shared.global [%0], [%1], 16;" :: "r"(s), "l"(g));
}
__device__ __forceinline__ uint32_t smem_u32(const void* p) {
    uint32_t a;
    asm("{ .reg .u64 t; cvta.to.shared.u64 t, %1; cvt.u32.u64 %0, t; }" : "=r"(a) : "l"(p));
    return a;
}
__device__ __forceinline__ uint32_t pack2(float a, float b) {
    return (uint32_t)__bfloat16_as_ushort(__float2bfloat16(a)) |
           ((uint32_t)__bfloat16_as_ushort(__float2bfloat16(b)) << 16);
}

// ---------------------------------------------------------------------------
// fp32 -> (bf16 hi, bf16 lo)   (vectorized x4)
// ---------------------------------------------------------------------------
__global__ void split_kernel(const float* __restrict__ s, __nv_bfloat16* __restrict__ h,
                             __nv_bfloat16* __restrict__ l, int n4)
{
    int i = blockIdx.x * 256 + threadIdx.x;
    if (i < n4) {
        float4 x = ((const float4*)s)[i];
        __nv_bfloat16 h0 = __float2bfloat16(x.x), h1 = __float2bfloat16(x.y);
        __nv_bfloat16 h2 = __float2bfloat16(x.z), h3 = __float2bfloat16(x.w);
        __nv_bfloat16 l0 = __float2bfloat16(x.x - __bfloat162float(h0));
        __nv_bfloat16 l1 = __float2bfloat16(x.y - __bfloat162float(h1));
        __nv_bfloat16 l2 = __float2bfloat16(x.z - __bfloat162float(h2));
        __nv_bfloat16 l3 = __float2bfloat16(x.w - __bfloat162float(h3));
        ushort4 hv, lv;
        hv.x = __bfloat16_as_ushort(h0); hv.y = __bfloat16_as_ushort(h1);
        hv.z = __bfloat16_as_ushort(h2); hv.w = __bfloat16_as_ushort(h3);
        lv.x = __bfloat16_as_ushort(l0); lv.y = __bfloat16_as_ushort(l1);
        lv.z = __bfloat16_as_ushort(l2); lv.w = __bfloat16_as_ushort(l3);
        ((ushort4*)h)[i] = hv;
        ((ushort4*)l)[i] = lv;
    }
}

// ---------------------------------------------------------------------------
// WMMA GEMM, 2-stage cp.async double buffer, vectorized epilogue.
// MODE 0: QKV 1-pass bf16, K-chunk 64
// MODE 1: dense 2-pass (A bf16 ctx, B hi/lo), K-chunk 64, fp32 out
// MODE 2: FFN1 3-pass, gelu, bf16 hi/lo out  MODE 3: FFN2 3-pass, fp32 out
// ---------------------------------------------------------------------------
template <int MODE>
__global__ __launch_bounds__(256, 2) void tc_gemm(const float* __restrict__ biasb, int zofs)
{
    constexpr int NPASS = (MODE == 0) ? 1 : ((MODE == 1) ? 2 : 3);
    constexpr int NBUF  = (MODE == 0) ? 2 : ((MODE == 1) ? 3 : 4);
    constexpr int KC    = (MODE <= 1) ? 64 : 32;
    constexpr int LDTc  = KC + 8;
    constexpr int BUFB  = 128 * LDTc * 2;
    constexpr int EBUF  = 128 * LDTc;
    constexpr int STG   = NBUF * BUFB;
    constexpr int SEGN  = KC / 8;
    constexpr int REPS  = (128 * SEGN) / 256;
    constexpr int BOFF_AL = 1;
    constexpr int BOFF_BH = (NPASS == 3) ? 2 : 1;
    constexpr int BOFF_BL = (NPASS == 3) ? 3 : 2;

    extern __shared__ char smem[];
    uint32_t sb = smem_u32(smem);

    int tid = threadIdx.x;
    int wid = tid >> 5, lane = tid & 31;
    int z = blockIdx.z + zofs;
    int m0 = blockIdx.y * 128, n0 = blockIdx.x * 128;

    const __nv_bfloat16 *A_h, *A_l = nullptr, *B_h, *B_l = nullptr;
    const float* bias = nullptr;
    float* Cf = nullptr;
    __nv_bfloat16 *Ch = nullptr, *Cl = nullptr;
    int K, N;
    if (MODE == 0) {
        K = Dd; N = QKVN;
        A_h = g_hid_h;
        B_h = g_Wqkv_h + (size_t)z * QKVN * Dd;
        Ch = g_qkv_h + (size_t)z * MROWS * QKVN;
    } else {
        int e = g_sel[z];
        if (MODE == 1) {
            K = Dd; N = Dd;
            A_h = g_ctx_b + ((size_t)(e * Bb + z)) * Ss_ * Dd;
            B_h = g_Wd_h + (size_t)e * Dd * Dd;  B_l = g_Wd_l + (size_t)e * Dd * Dd;
            bias = biasb + (size_t)e * Dd;
            Cf = g_att + (size_t)z * Ss_ * Dd;
        } else if (MODE == 2) {
            K = Dd; N = DFF;
            A_h = g_hb_h + (size_t)z * Ss_ * Dd;  A_l = g_hb_l + (size_t)z * Ss_ * Dd;
            B_h = g_W1_h + (size_t)e * DFF * Dd;  B_l = g_W1_l + (size_t)e * DFF * Dd;
            bias = biasb + (size_t)e * DFF;
            Ch = g_f1_h + (size_t)z * Ss_ * DFF;  Cl = g_f1_l + (size_t)z * Ss_ * DFF;
        } else {
            K = DFF; N = Dd;
            A_h = g_f1_h + (size_t)z * Ss_ * DFF; A_l = g_f1_l + (size_t)z * Ss_ * DFF;
            B_h = g_W2_h + (size_t)e * Dd * DFF;  B_l = g_W2_l + (size_t)e * Dd * DFF;
            bias = biasb + (size_t)e * Dd;
            Cf = g_ffn2 + (size_t)z * Ss_ * Dd;
        }
    }

    int wm = wid >> 2, wn = wid & 3;

    wmma::fragment<wmma::accumulator, 16, 16, 16, float> acc[4][2];
    #pragma unroll
    for (int i = 0; i < 4; i++)
        #pragma unroll
        for (int j = 0; j < 2; j++) wmma::fill_fragment(acc[i][j], 0.f);

    int row_[REPS], seg_[REPS];
    uint32_t sbo_[REPS];
    #pragma unroll
    for (int rep = 0; rep < REPS; rep++) {
        int idx = tid + rep * 256;
        row_[rep] = idx / SEGN; seg_[rep] = (idx % SEGN) * 8;
        sbo_[rep] = (uint32_t)(row_[rep] * LDTc + seg_[rep]) * 2;
    }

    const __nv_bfloat16* gA_h = A_h + (size_t)m0 * K;
    const __nv_bfloat16* gB_h = B_h + (size_t)n0 * K;
    const __nv_bfloat16* gA_l = (NPASS == 3) ? A_l + (size_t)m0 * K : nullptr;
    const __nv_bfloat16* gB_l = (NPASS >= 2) ? B_l + (size_t)n0 * K : nullptr;

    int KT = K / KC;

    #define ISSUE_STAGE(kcI, st) do {                                          \
        uint32_t base_ = sb + (uint32_t)(st) * STG;                            \
        _Pragma("unroll")                                                      \
        for (int rep = 0; rep < REPS; rep++) {                                 \
            size_t goff_ = (size_t)row_[rep] * K + (size_t)(kcI) * KC + seg_[rep]; \
            uint32_t so_ = base_ + sbo_[rep];                                  \
            cp16(so_, gA_h + goff_);                                           \
            if (NPASS == 3) cp16(so_ + BOFF_AL * BUFB, gA_l + goff_);          \
            cp16(so_ + BOFF_BH * BUFB, gB_h + goff_);                          \
            if (NPASS >= 2) cp16(so_ + BOFF_BL * BUFB, gB_l + goff_);          \
        }                                                                      \
        asm volatile("cp.async.commit_group;" ::: "memory");                   \
    } while (0)

    ISSUE_STAGE(0, 0);
    ISSUE_STAGE(1, 1);

    for (int kc = 0; kc < KT; kc++) {
        int st = kc & 1;
        if (kc + 1 < KT) asm volatile("cp.async.wait_group 1;" ::: "memory");
        else             asm volatile("cp.async.wait_group 0;" ::: "memory");
        __syncthreads();

        __nv_bfloat16* Ah = (__nv_bfloat16*)(smem + st * STG);
        __nv_bfloat16* Al = Ah + BOFF_AL * EBUF;
        __nv_bfloat16* Bh = Ah + BOFF_BH * EBUF;
        __nv_bfloat16* Bl = Ah + BOFF_BL * EBUF;
        #pragma unroll
        for (int kk = 0; kk < KC / 16; kk++) {
            int ko = kk * 16;
            wmma::fragment<wmma::matrix_a, 16, 16, 16, __nv_bfloat16, wmma::row_major> fa_h[4], fa_l[4];
            wmma::fragment<wmma::matrix_b, 16, 16, 16, __nv_bfloat16, wmma::col_major> fb_h[2], fb_l[2];
            #pragma unroll
            for (int i = 0; i < 4; i++) {
                wmma::load_matrix_sync(fa_h[i], &Ah[(wm * 64 + i * 16) * LDTc + ko], LDTc);
                if (NPASS == 3) wmma::load_matrix_sync(fa_l[i], &Al[(wm * 64 + i * 16) * LDTc + ko], LDTc);
            }
            #pragma unroll
            for (int j = 0; j < 2; j++) {
                wmma::load_matrix_sync(fb_h[j], &Bh[(wn * 32 + j * 16) * LDTc + ko], LDTc);
                if (NPASS >= 2) wmma::load_matrix_sync(fb_l[j], &Bl[(wn * 32 + j * 16) * LDTc + ko], LDTc);
            }
            #pragma unroll
            for (int i = 0; i < 4; i++)
                #pragma unroll
                for (int j = 0; j < 2; j++) {
                    wmma::mma_sync(acc[i][j], fa_h[i], fb_h[j], acc[i][j]);
                    if (NPASS >= 2) wmma::mma_sync(acc[i][j], fa_h[i], fb_l[j], acc[i][j]);
                    if (NPASS == 3) wmma::mma_sync(acc[i][j], fa_l[i], fb_h[j], acc[i][j]);
                }
        }
        if (kc + 2 < KT) {
            __syncthreads();
            ISSUE_STAGE(kc + 2, st);
        }
    }
    #undef ISSUE_STAGE

    __syncthreads();

    float* Stage = (float*)smem + wid * 256;
    int r = lane >> 1, c0 = (lane & 1) * 8;
    #pragma unroll
    for (int i = 0; i < 4; i++)
        #pragma unroll
        for (int j = 0; j < 2; j++) {
            wmma::store_matrix_sync(Stage, acc[i][j], 16, wmma::mem_row_major);
            __syncwarp();
            int gm = m0 + wm * 64 + i * 16 + r;
            int gn = n0 + wn * 32 + j * 16 + c0;
            const float* srow = Stage + r * 16 + c0;
            float vv[8];
            #pragma unroll
            for (int c = 0; c < 8; c++) {
                float v = srow[c];
                if (MODE != 0) v += bias[gn + c];
                if (MODE == 2) v = 0.5f * v * (1.f + erff(v * 0.7071067811865475f));
                vv[c] = v;
            }
            size_t ob = (size_t)gm * N + gn;
            if (MODE == 0) {
                uint4 pk;
                pk.x = pack2(vv[0], vv[1]); pk.y = pack2(vv[2], vv[3]);
                pk.z = pack2(vv[4], vv[5]); pk.w = pack2(vv[6], vv[7]);
                *(uint4*)&Ch[ob] = pk;
            } else if (MODE == 2) {
                uint32_t ph[4], pl[4];
                #pragma unroll
                for (int q = 0; q < 4; q++) {
                    __nv_bfloat16 h0 = __float2bfloat16(vv[2 * q]);
                    __nv_bfloat16 h1 = __float2bfloat16(vv[2 * q + 1]);
                    __nv_bfloat16 l0 = __float2bfloat16(vv[2 * q] - __bfloat162float(h0));
                    __nv_bfloat16 l1 = __float2bfloat16(vv[2 * q + 1] - __bfloat162float(h1));
                    ph[q] = __bfloat16_as_ushort(h0) | ((uint32_t)__bfloat16_as_ushort(h1) << 16);
                    pl[q] = __bfloat16_as_ushort(l0) | ((uint32_t)__bfloat16_as_ushort(l1) << 16);
                }
                uint4 vh; vh.x = ph[0]; vh.y = ph[1]; vh.z = ph[2]; vh.w = ph[3];
                uint4 vl; vl.x = pl[0]; vl.y = pl[1]; vl.z = pl[2]; vl.w = pl[3];
                *(uint4*)&Ch[ob] = vh;
                *(uint4*)&Cl[ob] = vl;
            } else {
                float4 f0; f0.x = vv[0]; f0.y = vv[1]; f0.z = vv[2]; f0.w = vv[3];
                float4 f1; f1.x = vv[4]; f1.y = vv[5]; f1.z = vv[6]; f1.w = vv[7];
                *(float4*)&Cf[ob] = f0;
                *(float4*)&Cf[ob + 4] = f1;
            }
            __syncwarp();
        }
}

// ---------------------------------------------------------------------------
// Pure-bf16 WMMA attention, cp.async 2-stage K/V ring, V overlaps softmax,
// Q fragments hoisted, bf16 ctx output. smem 90,112 B -> 2 CTAs/SM.
// ---------------------------------------------------------------------------
#define QT 32
#define SLD 524
#define PLD 1048
#define ATT_SC  0
#define ATT_Q   67072
#define ATT_K0  71680
#define KSTG2   9216
#define ATT_TOT 90112

__global__ __launch_bounds__(256, 2) void attn2_kernel(const int* __restrict__ mask, int ebofs)
{
    extern __shared__ char smem[];
    uint32_t sb = smem_u32(smem);
    float* Sc = (float*)(smem + ATT_SC);
    __nv_bfloat16* P = (__nv_bfloat16*)(smem + ATT_SC);
    __nv_bfloat16* Qs = (__nv_bfloat16*)(smem + ATT_Q);

    int q0 = blockIdx.x * QT;
    int h  = blockIdx.y;
    int eb = blockIdx.z + ebofs;
    int e = eb >> 3, b = eb & 7;
    int tid = threadIdx.x;
    int wid = tid >> 5, lane = tid & 31;
    int wr = wid >> 2, wc = wid & 3;

    const __nv_bfloat16* baseh = g_qkv_h + ((size_t)e * MROWS + b * Ss_) * QKVN + h * 192;

    float mb[16];
    #pragma unroll
    for (int t = 0; t < 16; t++)
        mb[t] = (mask[b * Ss_ + lane + t * 32] == 0) ? -1e30f : 0.f;

    #define ISSUE_KV(srcOff, ktI, st) do {                                       \
        uint32_t kb_ = sb + ATT_K0 + (uint32_t)(st) * KSTG2;                     \
        _Pragma("unroll")                                                        \
        for (int rep = 0; rep < 2; rep++) {                                      \
            int idx = tid + rep * 256;                                           \
            int row = idx >> 3, seg = (idx & 7) * 8;                             \
            size_t go = (size_t)((ktI) * 64 + row) * QKVN + (srcOff) + seg;      \
            cp16(kb_ + (uint32_t)(row * 72 + seg) * 2, baseh + go);              \
        }                                                                        \
    } while (0)

    {
        int row = tid >> 3, seg = (tid & 7) * 8;
        size_t go = (size_t)(q0 + row) * QKVN + seg;
        cp16(sb + ATT_Q + (uint32_t)(row * 72 + seg) * 2, baseh + go);
    }
    ISSUE_KV(64, 0, 0);
    asm volatile("cp.async.commit_group;" ::: "memory");
    ISSUE_KV(64, 1, 1);
    asm volatile("cp.async.commit_group;" ::: "memory");

    wmma::fragment<wmma::matrix_a, 16, 16, 16, __nv_bfloat16, wmma::row_major> qf[4];

    // ---- S = Q K^T ----
    for (int kt = 0; kt < 8; kt++) {
        int st = kt & 1;
        if (kt + 1 < 8) asm volatile("cp.async.wait_group 1;" ::: "memory");
        else            asm volatile("cp.async.wait_group 0;" ::: "memory");
        __syncthreads();
        if (kt == 0) {
            #pragma unroll
            for (int kf = 0; kf < 4; kf++)
                wmma::load_matrix_sync(qf[kf], &Qs[(wr * 16) * 72 + kf * 16], 72);
        }

        __nv_bfloat16* Kh = (__nv_bfloat16*)(smem + ATT_K0 + st * KSTG2);

        wmma::fragment<wmma::accumulator, 16, 16, 16, float> acc;
        wmma::fill_fragment(acc, 0.f);
        #pragma unroll
        for (int kf = 0; kf < 4; kf++) {
            wmma::fragment<wmma::matrix_b, 16, 16, 16, __nv_bfloat16, wmma::col_major> kh;
            wmma::load_matrix_sync(kh, &Kh[(wc * 16) * 72 + kf * 16], 72);
            wmma::mma_sync(acc, qf[kf], kh, acc);
        }
        wmma::store_matrix_sync(&Sc[(wr * 16) * SLD + kt * 64 + wc * 16], acc, SLD, wmma::mem_row_major);

        if (kt + 2 < 8) {
            __syncthreads();
            ISSUE_KV(64, kt + 2, st);
            asm volatile("cp.async.commit_group;" ::: "memory");
        }
    }
    __syncthreads();

    ISSUE_KV(128, 0, 0);
    asm volatile("cp.async.commit_group;" ::: "memory");
    ISSUE_KV(128, 1, 1);
    asm volatile("cp.async.commit_group;" ::: "memory");

    // ---- softmax; write P (bf16) aliased into this row's own Sc bytes ----
    {
        #pragma unroll
        for (int rr = 0; rr < 4; rr++) {
            int row = wid * 4 + rr;
            const float* srow = Sc + row * SLD;
            float v[16];
            float mx = -INFINITY;
            #pragma unroll
            for (int t = 0; t < 16; t++) {
                int j = lane + t * 32;
                v[t] = srow[j] * SCALE + mb[t];
                mx = fmaxf(mx, v[t]);
            }
            #pragma unroll
            for (int o = 16; o; o >>= 1) mx = fmaxf(mx, __shfl_xor_sync(~0u, mx, o));
            float sum = 0.f;
            #pragma unroll
            for (int t = 0; t < 16; t++) { v[t] = __expf(v[t] - mx); sum += v[t]; }
            #pragma unroll
            for (int o = 16; o; o >>= 1) sum += __shfl_xor_sync(~0u, sum, o);
            float inv = 1.f / sum;
            __nv_bfloat16* prow = P + row * PLD;
            #pragma unroll
            for (int t = 0; t < 16; t++) {
                int j = lane + t * 32;
                prow[j] = __float2bfloat16(v[t] * inv);
            }
        }
    }

    // ---- O = P V ----
    wmma::fragment<wmma::accumulator, 16, 16, 16, float> oacc;
    wmma::fill_fragment(oacc, 0.f);
    for (int vt = 0; vt < 8; vt++) {
        int st = vt & 1;
        if (vt + 1 < 8) asm volatile("cp.async.wait_group 1;" ::: "memory");
        else            asm volatile("cp.async.wait_group 0;" ::: "memory");
        __syncthreads();

        __nv_bfloat16* Vh = (__nv_bfloat16*)(smem + ATT_K0 + st * KSTG2);

        #pragma unroll
        for (int kf = 0; kf < 4; kf++) {
            wmma::fragment<wmma::matrix_a, 16, 16, 16, __nv_bfloat16, wmma::row_major> ph;
            wmma::fragment<wmma::matrix_b, 16, 16, 16, __nv_bfloat16, wmma::row_major> vh;
            wmma::load_matrix_sync(ph, &P[(wr * 16) * PLD + vt * 64 + kf * 16], PLD);
            wmma::load_matrix_sync(vh, &Vh[(kf * 16) * 72 + wc * 16], 72);
            wmma::mma_sync(oacc, ph, vh, oacc);
        }
        if (vt + 2 < 8) {
            __syncthreads();
            ISSUE_KV(128, vt + 2, st);
            asm volatile("cp.async.commit_group;" ::: "memory");
        }
    }
    #undef ISSUE_KV

    // ---- epilogue: stage oacc, write bf16 ctx (vectorized) ----
    __syncthreads();
    {
        float* StageW = (float*)smem + wid * 256;
        wmma::store_matrix_sync(StageW, oacc, 16, wmma::mem_row_major);
        __syncwarp();
        int r = lane >> 1, c0 = (lane & 1) * 8;
        const float* srow = StageW + r * 16 + c0;
        uint4 pk;
        pk.x = pack2(srow[0], srow[1]); pk.y = pack2(srow[2], srow[3]);
        pk.z = pack2(srow[4], srow[5]); pk.w = pack2(srow[6], srow[7]);
        __nv_bfloat16* op = g_ctx_b + ((size_t)eb * Ss_ + q0 + wr * 16 + r) * Dd + h * 64 + wc * 16 + c0;
        *(uint4*)op = pk;
    }
}

// ---------------------------------------------------------------------------
// routing
// ---------------------------------------------------------------------------
__global__ void zeroroute_kernel()
{
    int i = blockIdx.x * 256 + threadIdx.x;
    if (i < Ee * Bb * Dd) g_mean[i] = 0.f;
    if (i < Ee * Bb) g_dists[i] = 0.f;
}

__global__ void meanctx_kernel(int ebofs)
{
    int eb = blockIdx.x + ebofs;
    int chunk = blockIdx.y;
    int d = threadIdx.x;
    const __nv_bfloat16* p = g_ctx_b + ((size_t)eb * Ss_ + chunk * 64) * Dd + d;
    float s = 0.f;
    for (int i = 0; i < 64; i++) s += __bfloat162float(p[(size_t)i * Dd]);
    atomicAdd(&g_mean[eb * Dd + d], s * (1.f / Ss_));
}

__global__ __launch_bounds__(256) void featdist_kernel(const float* __restrict__ Wd,
                                                       const float* __restrict__ bd,
                                                       const float* __restrict__ centers)
{
    int eb = blockIdx.x, e = eb >> 3;
    int chunk = blockIdx.y;
    __shared__ float mn[Dd];
    int tid = threadIdx.x;
    for (int d = tid; d < Dd; d += 256) mn[d] = g_mean[eb * Dd + d];
    __syncthreads();
    int w = tid >> 5, lane = tid & 31;
    float sq = 0.f;
    for (int i = 0; i < 12; i++) {
        int d = chunk * 96 + w * 12 + i;
        const float* wrow = Wd + ((size_t)e * Dd + d) * Dd;
        float p = 0.f;
        for (int k = lane; k < Dd; k += 32) p += wrow[k] * mn[k];
        #pragma unroll
        for (int o = 16; o; o >>= 1) p += __shfl_xor_sync(~0u, p, o);
        if (lane == 0) {
            float f = p + bd[e * Dd + d] - centers[e * Dd + d];
            sq += f * f;
        }
    }
    if (lane == 0) atomicAdd(&g_dists[eb], sq);
}

__global__ void argmin_kernel()
{
    int b = threadIdx.x;
    if (b < Bb) {
        float best = g_dists[b];
        int bi = 0;
        for (int e = 1; e < Ee; e++) {
            float v = g_dists[e * Bb + b];
            if (v < best) { best = v; bi = e; }
        }
        g_sel[b] = bi;
    }
}

// ---------------------------------------------------------------------------
// residual + layernorm
// ---------------------------------------------------------------------------
__device__ __forceinline__ float block_sum_768(float v, float* red, int tid)
{
    __syncthreads();
    #pragma unroll
    for (int o = 16; o; o >>= 1) v += __shfl_xor_sync(~0u, v, o);
    if ((tid & 31) == 0) red[tid >> 5] = v;
    __syncthreads();
    if (tid < 8) {
        float t = red[tid];
        #pragma unroll
        for (int o = 4; o; o >>= 1) t += __shfl_xor_sync(0xffu, t, o);
        if (tid == 0) red[0] = t;
    }
    __syncthreads();
    return red[0];
}

template <int WHICH>
__global__ __launch_bounds__(256) void residual_ln_kernel(
    const float* __restrict__ X, const float* __restrict__ gamma_,
    const float* __restrict__ beta_, float* __restrict__ Out)
{
    __shared__ float red[8];
    int row = blockIdx.x;
    int b = row >> 9;
    int e = g_sel[b];
    const float* gamma = gamma_ + e * Dd;
    const float* beta  = beta_  + e * Dd;
    const float* xr; const float* yr; float* orow;
    if (WHICH == 1) {
        xr = X + (size_t)row * Dd;
        yr = g_att + (size_t)row * Dd;
        orow = g_h + (size_t)row * Dd;
    } else {
        xr = g_h + (size_t)row * Dd;
        yr = g_ffn2 + (size_t)row * Dd;
        orow = Out + (size_t)row * Dd;
    }
    int tid = threadIdx.x;
    float v0 = xr[tid] + yr[tid];
    float v1 = xr[tid + 256] + yr[tid + 256];
    float v2 = xr[tid + 512] + yr[tid + 512];
    float mean = block_sum_768(v0 + v1 + v2, red, tid) * (1.f / Dd);
    float d0 = v0 - mean, d1 = v1 - mean, d2 = v2 - mean;
    float var = block_sum_768(d0 * d0 + d1 * d1 + d2 * d2, red, tid) * (1.f / Dd);
    float inv = rsqrtf(var + EPS);
    float o0 = d0 * inv * gamma[tid]       + beta[tid];
    float o1 = d1 * inv * gamma[tid + 256] + beta[tid + 256];
    float o2 = d2 * inv * gamma[tid + 512] + beta[tid + 512];
    orow[tid]       = o0;
    orow[tid + 256] = o1;
    orow[tid + 512] = o2;
    if (WHICH == 1) {
        __nv_bfloat16* hh = g_hb_h + (size_t)row * Dd;
        __nv_bfloat16* hl = g_hb_l + (size_t)row * Dd;
        __nv_bfloat16 h0 = __float2bfloat16(o0);
        __nv_bfloat16 h1 = __float2bfloat16(o1);
        __nv_bfloat16 h2 = __float2bfloat16(o2);
        hh[tid] = h0;       hl[tid]       = __float2bfloat16(o0 - __bfloat162float(h0));
        hh[tid + 256] = h1; hl[tid + 256] = __float2bfloat16(o1 - __bfloat162float(h1));
        hh[tid + 512] = h2; hl[tid + 512] = __float2bfloat16(o2 - __bfloat162float(h2));
    }
}

// ---------------------------------------------------------------------------
// launch (R15 schedule; bf16 ctx path; featdist/argmin in tail)
// ---------------------------------------------------------------------------
#define SMEM_G1 (2 * 2 * (128 * 72 * 2))   // 73728  (QKV, 2 bufs, KC64)
#define SMEM_GD (2 * 3 * (128 * 72 * 2))   // 110592 (dense, 3 bufs, KC64)
#define SMEM_G3 (2 * 4 * (128 * 40 * 2))   // 81920  (FFN, 4 bufs, KC32)

extern "C" void kernel_launch(void* const* d_in, const int* in_sizes, int n_in,
                              void* d_out, int out_size)
{
    const float* hidden  = (const float*)d_in[0];
    const int*   mask    = (const int*)d_in[1];
    const float* Wqkv    = (const float*)d_in[2];
    const float* Wd      = (const float*)d_in[3];
    const float* bd      = (const float*)d_in[4];
    const float* ln1g    = (const float*)d_in[5];
    const float* ln1b    = (const float*)d_in[6];
    const float* W1      = (const float*)d_in[7];
    const float* b1      = (const float*)d_in[8];
    const float* W2      = (const float*)d_in[9];
    const float* b2      = (const float*)d_in[10];
    const float* ln2g    = (const float*)d_in[11];
    const float* ln2b    = (const float*)d_in[12];
    const float* centers = (const float*)d_in[13];
    float* out = (float*)d_out;

    static bool init_done = false;
    static cudaStream_t sB, sQ;
    static cudaEvent_t evFork, evJoin, evSplit, evQ[Ee], evA[Ee];
    if (!init_done) {
        cudaFuncSetAttribute(attn2_kernel, cudaFuncAttributeMaxDynamicSharedMemorySize, ATT_TOT);
        cudaFuncSetAttribute(tc_gemm<0>, cudaFuncAttributeMaxDynamicSharedMemorySize, SMEM_G1);
        cudaFuncSetAttribute(tc_gemm<1>, cudaFuncAttributeMaxDynamicSharedMemorySize, SMEM_GD);
        cudaFuncSetAttribute(tc_gemm<2>, cudaFuncAttributeMaxDynamicSharedMemorySize, SMEM_G3);
        cudaFuncSetAttribute(tc_gemm<3>, cudaFuncAttributeMaxDynamicSharedMemorySize, SMEM_G3);
        cudaStreamCreateWithFlags(&sB, cudaStreamNonBlocking);
        cudaStreamCreateWithFlags(&sQ, cudaStreamNonBlocking);
        cudaEventCreateWithFlags(&evFork, cudaEventDisableTiming);
        cudaEventCreateWithFlags(&evJoin, cudaEventDisableTiming);
        cudaEventCreateWithFlags(&evSplit, cudaEventDisableTiming);
        for (int e = 0; e < Ee; e++) {
            cudaEventCreateWithFlags(&evQ[e], cudaEventDisableTiming);
            cudaEventCreateWithFlags(&evA[e], cudaEventDisableTiming);
        }
        init_done = true;
    }

    __nv_bfloat16 *hid_h, *hid_l, *wq_h, *wq_l, *wd_h, *wd_l, *w1_h, *w1_l, *w2_h, *w2_l;
    cudaGetSymbolAddress((void**)&hid_h, g_hid_h);  cudaGetSymbolAddress((void**)&hid_l, g_hid_l);
    cudaGetSymbolAddress((void**)&wq_h, g_Wqkv_h);  cudaGetSymbolAddress((void**)&wq_l, g_Wqkv_l);
    cudaGetSymbolAddress((void**)&wd_h, g_Wd_h);    cudaGetSymbolAddress((void**)&wd_l, g_Wd_l);
    cudaGetSymbolAddress((void**)&w1_h, g_W1_h);    cudaGetSymbolAddress((void**)&w1_l, g_W1_l);
    cudaGetSymbolAddress((void**)&w2_h, g_W2_h);    cudaGetSymbolAddress((void**)&w2_l, g_W2_l);

    int n_hid = MROWS * Dd / 4;
    int n_wq  = Ee * QKVN * Dd / 4;
    int n_wd  = Ee * Dd * Dd / 4;
    int n_w1  = Ee * DFF * Dd / 4;
    int n_w2  = Ee * Dd * DFF / 4;

    cudaEventRecord(evFork, 0);

    // ---- main stream: input splits ----
    split_kernel<<<(n_hid + 255) / 256, 256>>>(hidden, hid_h, hid_l, n_hid);
    split_kernel<<<(n_wq  + 255) / 256, 256>>>(Wqkv,  wq_h,  wq_l,  n_wq);
    cudaEventRecord(evSplit, 0);

    // ---- stream Q: per-expert QKV GEMMs (serial on sQ) ----
    cudaStreamWaitEvent(sQ, evSplit, 0);
    for (int e = 0; e < Ee; e++) {
        tc_gemm<0><<<dim3(QKVN / 128, MROWS / 128, 1), 256, SMEM_G1, sQ>>>(nullptr, e);
        cudaEventRecord(evQ[e], sQ);
    }

    // ---- main stream: per-expert attention, each gated on its QKV ----
    for (int e = 0; e < Ee; e++) {
        cudaStreamWaitEvent(0, evQ[e], 0);
        attn2_kernel<<<dim3(Ss_ / QT, Hh, Bb), 256, ATT_TOT>>>(mask, e * Bb);
        cudaEventRecord(evA[e], 0);
    }

    // ---- side stream: zeroroute, weight splits, per-expert meanctx (R15 schedule) ----
    cudaStreamWaitEvent(sB, evFork, 0);
    zeroroute_kernel<<<(Ee * Bb * Dd + 255) / 256, 256, 0, sB>>>();
    split_kernel<<<(n_wd + 255) / 256, 256, 0, sB>>>(Wd, wd_h, wd_l, n_wd);
    split_kernel<<<(n_w1 + 255) / 256, 256, 0, sB>>>(W1, w1_h, w1_l, n_w1);
    split_kernel<<<(n_w2 + 255) / 256, 256, 0, sB>>>(W2, w2_h, w2_l, n_w2);
    for (int e = 0; e < Ee; e++) {
        cudaStreamWaitEvent(sB, evA[e], 0);
        meanctx_kernel<<<dim3(Bb, 8), Dd, 0, sB>>>(e * Bb);
    }
    cudaEventRecord(evJoin, sB);

    cudaStreamWaitEvent(0, evJoin, 0);

    featdist_kernel<<<dim3(Ee * Bb, 8), 256>>>(Wd, bd, centers);
    argmin_kernel<<<1, 32>>>();
    // selected-expert path (no ctxsel needed; dense reads bf16 ctx directly)
    tc_gemm<1><<<dim3(Dd / 128, Ss_ / 128, Bb), 256, SMEM_GD>>>(bd, 0);
    residual_ln_kernel<1><<<MROWS, 256>>>(hidden, ln1g, ln1b, nullptr);
    tc_gemm<2><<<dim3(DFF / 128, Ss_ / 128, Bb), 256, SMEM_G3>>>(b1, 0);
    tc_gemm<3><<<dim3(Dd / 128, Ss_ / 128, Bb), 256, SMEM_G3>>>(b2, 0);
    residual_ln_kernel<2><<<MROWS, 256>>>(nullptr, ln2g, ln2b, out);
}